// round 1
// baseline (speedup 1.0000x reference)
#include <cuda_runtime.h>
#include <cuda_bf16.h>
#include <cstdint>

// Problem constants
#define N_REL   65536
#define D_FEAT  3872
#define D_OUT   512
#define N_CLS   36

// ---------------- device scratch (no allocations allowed) ----------------
__device__ int g_cnt[N_CLS];
__device__ int g_off[N_CLS + 1];
__device__ int g_poff[N_CLS];
__device__ int g_sorted[N_REL];
__device__ int g_lo[N_REL];
__device__ int g_hi[N_REL];

// ---------------- index-construction kernels ----------------
__global__ void k_zero() {
    int t = threadIdx.x;
    if (t < N_CLS) g_cnt[t] = 0;
}

__global__ void k_hist(const int* __restrict__ lab) {
    int i = blockIdx.x * blockDim.x + threadIdx.x;
    if (i < N_REL) atomicAdd(&g_cnt[lab[i]], 1);
}

__global__ void k_scan() {
    // single thread: 36 elements
    if (threadIdx.x == 0) {
        int run = 0, prun = 0;
        g_off[0] = 0;
        for (int c = 0; c < N_CLS; c++) {
            g_poff[c] = prun;
            int cnt = g_cnt[c];
            run += cnt;
            g_off[c + 1] = run;
            prun += (cnt > 0) ? (cnt - 1) : 0;
        }
    }
}

// Block c computes stable rank of every row with label c; writes sorted order.
__global__ void k_rank(const int* __restrict__ lab) {
    const int c = blockIdx.x;
    const int tid = threadIdx.x;
    __shared__ int wsum[8];
    const int base_off = g_off[c];
    int sbase = 0;
    for (int start = 0; start < N_REL; start += 256) {
        int i = start + tid;                // N_REL % 256 == 0
        int flag = (lab[i] == c) ? 1 : 0;
        unsigned mask = __ballot_sync(0xffffffffu, flag);
        if ((tid & 31) == 0) wsum[tid >> 5] = __popc(mask);
        __syncthreads();
        int wbase = 0, total = 0;
        int wi = tid >> 5;
        #pragma unroll
        for (int j = 0; j < 8; j++) {
            int v = wsum[j];
            total += v;
            if (j < wi) wbase += v;
        }
        if (flag) {
            int excl = __popc(mask & ((1u << (tid & 31)) - 1u));
            g_sorted[base_off + sbase + wbase + excl] = i;
        }
        sbase += total;
        __syncthreads();
    }
}

__global__ void k_pairs(const int* __restrict__ lab) {
    int p = blockIdx.x * blockDim.x + threadIdx.x;
    if (p >= N_REL) return;
    int io = g_sorted[p];
    int c = lab[io];
    if (p + 1 < g_off[c + 1]) {           // next sorted row is same label
        int m = p - g_off[c] + g_poff[c];
        g_lo[m] = io;
        g_hi[m] = g_sorted[p + 1];
    }
}

// ---------------- fused gather-diff GEMM ----------------
// C[m, n_all] = (X[hi[m]] - X[lo[m]]) @ W_w + b_w
// Tile: 128(M) x 128(N) x 16(K), 256 threads, 8x8 per-thread microtile.
__global__ __launch_bounds__(256, 2)
void k_gemm(const float* __restrict__ X,
            const float* __restrict__ Wa, const float* __restrict__ ba,
            const float* __restrict__ Ws, const float* __restrict__ bs,
            const float* __restrict__ Wc, const float* __restrict__ bc,
            float* __restrict__ out, int M) {
    __shared__ float As[16][128];
    __shared__ float Bs[16][128];
    __shared__ int s_lo[128], s_hi[128];

    const int tid = threadIdx.x;
    const int tx = tid & 15;         // 0..15  (N dim)
    const int ty = tid >> 4;         // 0..15  (M dim)

    const int nb = blockIdx.x;       // 0..11
    const int w  = nb >> 2;          // which weight matrix
    const int n0 = (nb & 3) * 128;   // column base within that matrix

    const float* __restrict__ W    = (w == 0) ? Wa : ((w == 1) ? Ws : Wc);
    const float* __restrict__ bias = (w == 0) ? ba : ((w == 1) ? bs : bc);

    // gather indices for this M tile
    if (tid < 128) {
        int m = blockIdx.y * 128 + tid;      // always < N_REL
        s_lo[tid] = g_lo[m];
        s_hi[tid] = g_hi[m];
    }
    __syncthreads();

    float acc[8][8];
    #pragma unroll
    for (int i = 0; i < 8; i++)
        #pragma unroll
        for (int j = 0; j < 8; j++) acc[i][j] = 0.0f;

    for (int k0 = 0; k0 < D_FEAT; k0 += 16) {
        // --- load A tile: diff rows, transposed into As[k][m] ---
        #pragma unroll
        for (int jj = 0; jj < 2; jj++) {
            int idx = tid * 2 + jj;          // 0..511
            int row = idx >> 2;              // 0..127
            int kq  = idx & 3;               // 0..3 (float4 within K=16)
            int lo = s_lo[row], hi = s_hi[row];
            const float4 vh = *(const float4*)(X + (size_t)hi * D_FEAT + k0 + kq * 4);
            const float4 vl = *(const float4*)(X + (size_t)lo * D_FEAT + k0 + kq * 4);
            As[kq * 4 + 0][row] = vh.x - vl.x;
            As[kq * 4 + 1][row] = vh.y - vl.y;
            As[kq * 4 + 2][row] = vh.z - vl.z;
            As[kq * 4 + 3][row] = vh.w - vl.w;
        }
        // --- load B tile: Bs[k][n] ---
        #pragma unroll
        for (int jj = 0; jj < 2; jj++) {
            int l  = tid * 2 + jj;           // 0..511
            int k  = l >> 5;                 // 0..15
            int nq = l & 31;                 // 0..31
            *(float4*)&Bs[k][nq * 4] =
                *(const float4*)(W + (size_t)(k0 + k) * D_OUT + n0 + nq * 4);
        }
        __syncthreads();

        #pragma unroll
        for (int k = 0; k < 16; k++) {
            float4 a0 = *(const float4*)&As[k][ty * 8];
            float4 a1 = *(const float4*)&As[k][ty * 8 + 4];
            float4 b0 = *(const float4*)&Bs[k][tx * 8];
            float4 b1 = *(const float4*)&Bs[k][tx * 8 + 4];
            float av[8] = {a0.x, a0.y, a0.z, a0.w, a1.x, a1.y, a1.z, a1.w};
            float bv[8] = {b0.x, b0.y, b0.z, b0.w, b1.x, b1.y, b1.z, b1.w};
            #pragma unroll
            for (int i = 0; i < 8; i++)
                #pragma unroll
                for (int j = 0; j < 8; j++)
                    acc[i][j] = fmaf(av[i], bv[j], acc[i][j]);
        }
        __syncthreads();
    }

    // epilogue: add bias, write out[(w*M + m)*512 + col]
    float bv[8];
    #pragma unroll
    for (int j = 0; j < 8; j++) bv[j] = bias[n0 + tx * 8 + j];

    #pragma unroll
    for (int i = 0; i < 8; i++) {
        int gm = blockIdx.y * 128 + ty * 8 + i;
        if (gm < M) {
            float* dst = out + ((size_t)w * M + gm) * D_OUT + n0 + tx * 8;
            float4 o0, o1;
            o0.x = acc[i][0] + bv[0]; o0.y = acc[i][1] + bv[1];
            o0.z = acc[i][2] + bv[2]; o0.w = acc[i][3] + bv[3];
            o1.x = acc[i][4] + bv[4]; o1.y = acc[i][5] + bv[5];
            o1.z = acc[i][6] + bv[6]; o1.w = acc[i][7] + bv[7];
            *(float4*)(dst)     = o0;
            *(float4*)(dst + 4) = o1;
        }
    }
}

// ---------------- launch ----------------
extern "C" void kernel_launch(void* const* d_in, const int* in_sizes, int n_in,
                              void* d_out, int out_size) {
    const float* X  = (const float*)d_in[0];
    const float* Wa = (const float*)d_in[1];
    const float* ba = (const float*)d_in[2];
    const float* Ws = (const float*)d_in[3];
    const float* bs = (const float*)d_in[4];
    const float* Wc = (const float*)d_in[5];
    const float* bc = (const float*)d_in[6];
    const int*   lab = (const int*)d_in[7];
    float* out = (float*)d_out;

    const int M = out_size / (3 * D_OUT);   // rows of each output head

    k_zero<<<1, 64>>>();
    k_hist<<<N_REL / 256, 256>>>(lab);
    k_scan<<<1, 32>>>();
    k_rank<<<N_CLS, 256>>>(lab);
    k_pairs<<<N_REL / 256, 256>>>(lab);

    dim3 grid(12, (M + 127) / 128);
    k_gemm<<<grid, 256>>>(X, Wa, ba, Ws, bs, Wc, bc, out, M);
}

// round 3
// speedup vs baseline: 4.3744x; 4.3744x over previous
#include <cuda_runtime.h>
#include <cuda_bf16.h>
#include <cstdint>

#define N_REL   65536
#define D_FEAT  3872
#define D_OUT   512
#define N_CLS   36
#define NTOT    1536            // 3 heads * 512
#define KCHUNK  32              // floats per K tile (128 bytes)
#define NK      (D_FEAT / KCHUNK)   // 121
#define TM      128
#define TN      256
#define STAGES  2

// tcgen05 only exists in the arch-specific (sm_103a/sm_100a) device pass.
// The harness fatbin also builds a plain compute_103 PTX pass; give it a
// SIMT fallback body so ptxas succeeds there.
#if defined(__CUDA_ARCH_FEAT_SM103_ALL) || defined(__CUDA_ARCH_FEAT_SM100_ALL) || defined(__CUDA_ARCH_FEAT_SM101_ALL)
#define HAS_TCGEN05 1
#else
#define HAS_TCGEN05 0
#endif

// ---------------- device scratch ----------------
__device__ int g_cnt[N_CLS];
__device__ int g_off[N_CLS + 1];
__device__ int g_poff[N_CLS];
__device__ int g_sorted[N_REL];
__device__ int g_lo[N_REL];
__device__ int g_hi[N_REL];
__device__ float g_wt[(size_t)NTOT * D_FEAT];          // 24 MB, K-major weights
__device__ float g_diff[(size_t)N_REL * D_FEAT];       // ~1.01 GB, rows>=M stay 0

// ---------------- PTX helpers (expanded only in guarded code) ----------------
__device__ __forceinline__ uint32_t smem_to_u32(const void* p) {
    uint32_t a;
    asm("{ .reg .u64 t; cvta.to.shared.u64 t, %1; cvt.u32.u64 %0, t; }" : "=r"(a) : "l"(p));
    return a;
}
#define MBARRIER_INIT(mbar, cnt) \
    asm volatile("mbarrier.init.shared.b64 [%0], %1;" :: "r"((uint32_t)(mbar)), "r"((uint32_t)(cnt)) : "memory")
#define MBARRIER_WAIT_PARITY(mbar, par) do {                                        \
    uint32_t _m = (uint32_t)(mbar); uint32_t _p = (uint32_t)(par); uint32_t _d;     \
    asm volatile("{\n\t.reg .pred p;\n\t"                                           \
        "mbarrier.try_wait.parity.acquire.cta.shared::cta.b64 p, [%1], %2;\n\t"     \
        "selp.b32 %0, 1, 0, p;\n\t}" : "=r"(_d) : "r"(_m), "r"(_p) : "memory");     \
    if (!_d) {                                                                      \
        asm volatile("{\n\t.reg .pred P1;\n\t"                                      \
        "WL_%=:\n\tmbarrier.try_wait.parity.acquire.cta.shared::cta.b64 P1, [%0], %1, 0x989680;\n\t" \
        "@P1 bra.uni WD_%=;\n\tbra.uni WL_%=;\n\tWD_%=:\n\t}"                       \
        :: "r"(_m), "r"(_p) : "memory");                                            \
    } } while (0)
#define SMEM_SWIZZLE_128B(o)   ((o) ^ (((o) >> 3) & 0x70))
#define FENCE_ASYNC_SHARED()   asm volatile("fence.proxy.async.shared::cta;" ::: "memory")

#if HAS_TCGEN05
__device__ __forceinline__ uint32_t elect_one_pred() {
    uint32_t pred;
    asm volatile("{\n\t.reg .pred p;\n\telect.sync _|p, 0xFFFFFFFF;\n\tselp.b32 %0, 1, 0, p;\n\t}"
                 : "=r"(pred));
    return pred;
}
#define TCGEN05_ALLOC(sr, nc) \
    asm volatile("tcgen05.alloc.cta_group::1.sync.aligned.shared::cta.b32 [%0], %1;" \
                 :: "r"((uint32_t)(sr)), "r"((uint32_t)(nc)) : "memory")
#define TCGEN05_DEALLOC(t, nc) \
    asm volatile("tcgen05.dealloc.cta_group::1.sync.aligned.b32 %0, %1;" :: "r"(t), "r"((uint32_t)(nc)))
#define TCGEN05_RELINQ() \
    asm volatile("tcgen05.relinquish_alloc_permit.cta_group::1.sync.aligned;")
#define TCGEN05_COMMIT(mbar) \
    asm volatile("tcgen05.commit.cta_group::1.mbarrier::arrive::one.shared::cluster.b64 [%0];" \
                 :: "r"((uint32_t)(mbar)) : "memory")
#define TCGEN05_FENCE_AFTER()  asm volatile("tcgen05.fence::after_thread_sync;" ::: "memory")
#define TCGEN05_FENCE_BEFORE() asm volatile("tcgen05.fence::before_thread_sync;" ::: "memory")
#define TCGEN05_WAIT_LD()      asm volatile("tcgen05.wait::ld.sync.aligned;" ::: "memory")
#define TCGEN05_LD_X32(r, ta) \
    asm volatile("tcgen05.ld.sync.aligned.32x32b.x32.b32 " \
        "{%0,%1,%2,%3,%4,%5,%6,%7,%8,%9,%10,%11,%12,%13,%14,%15," \
        "%16,%17,%18,%19,%20,%21,%22,%23,%24,%25,%26,%27,%28,%29,%30,%31}, [%32];" \
        : "=r"((r)[0]),"=r"((r)[1]),"=r"((r)[2]),"=r"((r)[3]),"=r"((r)[4]),"=r"((r)[5]),"=r"((r)[6]),"=r"((r)[7]), \
          "=r"((r)[8]),"=r"((r)[9]),"=r"((r)[10]),"=r"((r)[11]),"=r"((r)[12]),"=r"((r)[13]),"=r"((r)[14]),"=r"((r)[15]), \
          "=r"((r)[16]),"=r"((r)[17]),"=r"((r)[18]),"=r"((r)[19]),"=r"((r)[20]),"=r"((r)[21]),"=r"((r)[22]),"=r"((r)[23]), \
          "=r"((r)[24]),"=r"((r)[25]),"=r"((r)[26]),"=r"((r)[27]),"=r"((r)[28]),"=r"((r)[29]),"=r"((r)[30]),"=r"((r)[31]) \
        : "r"(ta))

static constexpr uint64_t SMEM_DESC_BASE_SW128 =
    (uint64_t(2) << 61) | (uint64_t(1) << 46) | (uint64_t(64) << 32) | (uint64_t(1) << 16);
__device__ __forceinline__ uint64_t make_desc(uint32_t addr) {
    return SMEM_DESC_BASE_SW128 | ((uint64_t)(addr >> 4) & 0x3FFF);
}
__device__ __forceinline__ void mma_tf32_ss(uint32_t d, uint64_t a, uint64_t b,
                                            uint32_t idesc, uint32_t en) {
    asm volatile("{\n\t.reg .pred p;\n\tsetp.ne.u32 p, %5, 0;\n\t"
        "tcgen05.mma.cta_group::1.kind::tf32 [%0], %1, %2, %3, {%4, %4, %4, %4}, p;\n\t}"
        :: "r"(d), "l"(a), "l"(b), "r"(idesc), "r"(0u), "r"(en) : "memory");
}
// dtype=f32(1)<<4 | atype=tf32(2)<<7 | btype=tf32(2)<<10 | (N/8)<<17 | (M/16)<<24
static constexpr uint32_t IDESC = (1u << 4) | (2u << 7) | (2u << 10) |
                                  ((TN / 8) << 17) | ((TM / 16) << 24);
#endif  // HAS_TCGEN05

// ---------------- index construction ----------------
__global__ void k_zero() { if (threadIdx.x < N_CLS) g_cnt[threadIdx.x] = 0; }

__global__ void k_hist(const int* __restrict__ lab) {
    int i = blockIdx.x * blockDim.x + threadIdx.x;
    if (i < N_REL) atomicAdd(&g_cnt[lab[i]], 1);
}
__global__ void k_scan() {
    if (threadIdx.x == 0) {
        int run = 0, prun = 0;
        g_off[0] = 0;
        for (int c = 0; c < N_CLS; c++) {
            g_poff[c] = prun;
            int cnt = g_cnt[c];
            run += cnt; g_off[c + 1] = run;
            prun += (cnt > 0) ? (cnt - 1) : 0;
        }
    }
}
__global__ void k_rank(const int* __restrict__ lab) {
    const int c = blockIdx.x, tid = threadIdx.x;
    __shared__ int wsum[8];
    const int base_off = g_off[c];
    int sbase = 0;
    for (int start = 0; start < N_REL; start += 256) {
        int i = start + tid;
        int flag = (lab[i] == c) ? 1 : 0;
        unsigned mask = __ballot_sync(0xffffffffu, flag);
        if ((tid & 31) == 0) wsum[tid >> 5] = __popc(mask);
        __syncthreads();
        int wbase = 0, total = 0, wi = tid >> 5;
        #pragma unroll
        for (int j = 0; j < 8; j++) { int v = wsum[j]; total += v; if (j < wi) wbase += v; }
        if (flag) {
            int excl = __popc(mask & ((1u << (tid & 31)) - 1u));
            g_sorted[base_off + sbase + wbase + excl] = i;
        }
        sbase += total;
        __syncthreads();
    }
}
__global__ void k_pairs(const int* __restrict__ lab) {
    int p = blockIdx.x * blockDim.x + threadIdx.x;
    if (p >= N_REL) return;
    int io = g_sorted[p];
    int c = lab[io];
    if (p + 1 < g_off[c + 1]) {
        int m = p - g_off[c] + g_poff[c];
        g_lo[m] = io; g_hi[m] = g_sorted[p + 1];
    }
}

// ---------------- materialize diff rows ----------------
__global__ void k_diff(const float* __restrict__ X) {
    int m = blockIdx.x;
    int lo = g_lo[m], hi = g_hi[m];
    const float4* rl = (const float4*)(X + (size_t)lo * D_FEAT);
    const float4* rh = (const float4*)(X + (size_t)hi * D_FEAT);
    float4* dst = (float4*)(g_diff + (size_t)m * D_FEAT);
    for (int q = threadIdx.x; q < D_FEAT / 4; q += 256) {
        float4 a = rh[q], b = rl[q];
        float4 d; d.x = a.x - b.x; d.y = a.y - b.y; d.z = a.z - b.z; d.w = a.w - b.w;
        dst[q] = d;
    }
}

// ---------------- transpose weights to K-major ----------------
__global__ void k_wt(const float* __restrict__ Wa, const float* __restrict__ Ws,
                     const float* __restrict__ Wc) {
    __shared__ float tile[32][33];
    int kb = blockIdx.x * 32;
    int ng = blockIdx.y;
    int head = ng >> 4;
    const float* W = (head == 0) ? Wa : ((head == 1) ? Ws : Wc);
    int nb = (ng & 15) * 32;
    int tx = threadIdx.x, ty = threadIdx.y;  // (32, 8)
    #pragma unroll
    for (int r = 0; r < 4; r++) {
        int k = kb + ty + r * 8;
        tile[ty + r * 8][tx] = W[(size_t)k * D_OUT + nb + tx];
    }
    __syncthreads();
    #pragma unroll
    for (int r = 0; r < 4; r++) {
        int n = ng * 32 + ty + r * 8;
        g_wt[(size_t)n * D_FEAT + kb + tx] = tile[tx][ty + r * 8];
    }
}

// ---------------- GEMM: out = diff @ Wt^T + bias ----------------
// grid: x = 6 N-tiles (256 cols), y = 512 M-tiles (128 rows); 256 threads.
__global__ __launch_bounds__(256, 2)
void k_gemm(const float* __restrict__ Wa, const float* __restrict__ Ws,
            const float* __restrict__ Wc,
            const float* __restrict__ ba, const float* __restrict__ bs,
            const float* __restrict__ bc, float* __restrict__ out, int M) {
    extern __shared__ char smem[];
#if HAS_TCGEN05
    // ======================= tcgen05 tf32 path =======================
    const uint32_t sb = smem_to_u32(smem);
    const uint32_t mbar0 = sb + 8;
    const uint32_t mbar1 = sb + 16;
    const uint32_t data = (sb + 24 + 1023) & ~1023u;
    char* datap = smem + (data - sb);

    const int tid = threadIdx.x;
    const int wid = tid >> 5;
    const int lid = tid & 31;
    const int m0 = blockIdx.y * TM;
    const int n0 = blockIdx.x * TN;

    if (wid == 0) TCGEN05_ALLOC(sb, 256);
    if (tid == 0) { MBARRIER_INIT(mbar0, 1); MBARRIER_INIT(mbar1, 1); }
    __syncthreads();
    uint32_t tmem;
    asm volatile("ld.shared.b32 %0, [%1];" : "=r"(tmem) : "r"(sb));

    const uint32_t A_off[2] = { 0u, 49152u };
    const uint32_t B_off[2] = { 16384u, 65536u };

    const float* __restrict__ Asrc = g_diff + (size_t)m0 * D_FEAT;
    const float* __restrict__ Bsrc = g_wt + (size_t)n0 * D_FEAT;

    for (int i = 0; i < NK; i++) {
        const int s = i & 1;
        const uint32_t mb = s ? mbar1 : mbar0;
        if (i >= STAGES) {
            uint32_t par = ((i >> 1) - 1) & 1;
            MBARRIER_WAIT_PARITY(mb, par);
        }
        const int k0 = i * KCHUNK;
        {   // A tile: 128 rows x 32 floats
            char* As = datap + A_off[s];
            #pragma unroll
            for (int j = 0; j < 4; j++) {
                int e = j * 256 + tid;
                int row = e >> 3, q = e & 7;
                float4 v = *(const float4*)(Asrc + (size_t)row * D_FEAT + k0 + q * 4);
                uint32_t off = SMEM_SWIZZLE_128B((uint32_t)(row * 128 + q * 16));
                *(float4*)(As + off) = v;
            }
        }
        {   // B tile: 256 rows x 32 floats
            char* Bs = datap + B_off[s];
            #pragma unroll
            for (int j = 0; j < 8; j++) {
                int e = j * 256 + tid;
                int row = e >> 3, q = e & 7;
                float4 v = *(const float4*)(Bsrc + (size_t)row * D_FEAT + k0 + q * 4);
                uint32_t off = SMEM_SWIZZLE_128B((uint32_t)(row * 128 + q * 16));
                *(float4*)(Bs + off) = v;
            }
        }
        FENCE_ASYNC_SHARED();
        __syncthreads();
        if (wid == 0) {
            if (elect_one_pred()) {
                uint64_t ad = make_desc(data + A_off[s]);
                uint64_t bd = make_desc(data + B_off[s]);
                #pragma unroll
                for (int ks = 0; ks < 4; ks++) {
                    mma_tf32_ss(tmem, ad + ks * 2, bd + ks * 2, IDESC,
                                (i > 0 || ks > 0) ? 1u : 0u);
                }
                TCGEN05_COMMIT(mb);
            }
        }
    }
    MBARRIER_WAIT_PARITY((NK - 1) & 1 ? mbar1 : mbar0, ((NK - 1) >> 1) & 1);
    TCGEN05_FENCE_AFTER();

    const int head = n0 / D_OUT;
    const int ncl = n0 % D_OUT;
    const float* __restrict__ bias = (head == 0) ? ba : ((head == 1) ? bs : bc);
    const int wcol = (wid >= 4) ? 128 : 0;
    const int m = m0 + (wid & 3) * 32 + lid;

    #pragma unroll
    for (int cc = 0; cc < 128; cc += 32) {
        uint32_t r[32];
        TCGEN05_LD_X32(r, tmem + wcol + cc);
        TCGEN05_WAIT_LD();
        if (m < M) {
            int col = ncl + wcol + cc;
            float* dst = out + ((size_t)head * M + m) * D_OUT + col;
            #pragma unroll
            for (int q = 0; q < 8; q++) {
                float4 o;
                o.x = __uint_as_float(r[q * 4 + 0]) + bias[col + q * 4 + 0];
                o.y = __uint_as_float(r[q * 4 + 1]) + bias[col + q * 4 + 1];
                o.z = __uint_as_float(r[q * 4 + 2]) + bias[col + q * 4 + 2];
                o.w = __uint_as_float(r[q * 4 + 3]) + bias[col + q * 4 + 3];
                *(float4*)(dst + q * 4) = o;
            }
        }
    }
    TCGEN05_FENCE_BEFORE();
    __syncthreads();
    if (wid == 0) {
        TCGEN05_RELINQ();
        TCGEN05_DEALLOC(tmem, 256);
    }
#else
    // ======================= SIMT fallback (compute_103 pass) =======================
    float (*As)[128] = (float(*)[128])smem;                       // [16][128]
    float (*Bs)[128] = (float(*)[128])(smem + 16 * 128 * 4);      // [16][128]
    const int tid = threadIdx.x;
    const int tx = tid & 15;
    const int ty = tid >> 4;
    const int m0 = blockIdx.y * TM;

    for (int h = 0; h < 2; h++) {
        const int n0 = blockIdx.x * TN + h * 128;
        const int head = n0 / D_OUT;
        const int ncl = n0 % D_OUT;
        const float* __restrict__ W    = (head == 0) ? Wa : ((head == 1) ? Ws : Wc);
        const float* __restrict__ bias = (head == 0) ? ba : ((head == 1) ? bs : bc);

        float acc[8][8];
        #pragma unroll
        for (int i = 0; i < 8; i++)
            #pragma unroll
            for (int j = 0; j < 8; j++) acc[i][j] = 0.0f;

        for (int k0 = 0; k0 < D_FEAT; k0 += 16) {
            #pragma unroll
            for (int jj = 0; jj < 2; jj++) {
                int idx = tid * 2 + jj;
                int row = idx >> 2, kq = idx & 3;
                float4 v = *(const float4*)(g_diff + (size_t)(m0 + row) * D_FEAT + k0 + kq * 4);
                As[kq * 4 + 0][row] = v.x; As[kq * 4 + 1][row] = v.y;
                As[kq * 4 + 2][row] = v.z; As[kq * 4 + 3][row] = v.w;
            }
            #pragma unroll
            for (int jj = 0; jj < 2; jj++) {
                int l = tid * 2 + jj;
                int k = l >> 5, nq = l & 31;
                *(float4*)&Bs[k][nq * 4] =
                    *(const float4*)(W + (size_t)(k0 + k) * D_OUT + ncl + nq * 4);
            }
            __syncthreads();
            #pragma unroll
            for (int k = 0; k < 16; k++) {
                float4 a0 = *(const float4*)&As[k][ty * 8];
                float4 a1 = *(const float4*)&As[k][ty * 8 + 4];
                float4 b0 = *(const float4*)&Bs[k][tx * 8];
                float4 b1 = *(const float4*)&Bs[k][tx * 8 + 4];
                float av[8] = {a0.x, a0.y, a0.z, a0.w, a1.x, a1.y, a1.z, a1.w};
                float bv[8] = {b0.x, b0.y, b0.z, b0.w, b1.x, b1.y, b1.z, b1.w};
                #pragma unroll
                for (int i = 0; i < 8; i++)
                    #pragma unroll
                    for (int j = 0; j < 8; j++)
                        acc[i][j] = fmaf(av[i], bv[j], acc[i][j]);
            }
            __syncthreads();
        }

        float bv[8];
        #pragma unroll
        for (int j = 0; j < 8; j++) bv[j] = bias[ncl + tx * 8 + j];
        #pragma unroll
        for (int i = 0; i < 8; i++) {
            int gm = m0 + ty * 8 + i;
            if (gm < M) {
                float* dst = out + ((size_t)head * M + gm) * D_OUT + ncl + tx * 8;
                float4 o0, o1;
                o0.x = acc[i][0] + bv[0]; o0.y = acc[i][1] + bv[1];
                o0.z = acc[i][2] + bv[2]; o0.w = acc[i][3] + bv[3];
                o1.x = acc[i][4] + bv[4]; o1.y = acc[i][5] + bv[5];
                o1.z = acc[i][6] + bv[6]; o1.w = acc[i][7] + bv[7];
                *(float4*)(dst)     = o0;
                *(float4*)(dst + 4) = o1;
            }
        }
        __syncthreads();
    }
#endif
}

// ---------------- launch ----------------
extern "C" void kernel_launch(void* const* d_in, const int* in_sizes, int n_in,
                              void* d_out, int out_size) {
    const float* X   = (const float*)d_in[0];
    const float* Wa  = (const float*)d_in[1];
    const float* ba  = (const float*)d_in[2];
    const float* Ws  = (const float*)d_in[3];
    const float* bs  = (const float*)d_in[4];
    const float* Wc  = (const float*)d_in[5];
    const float* bc  = (const float*)d_in[6];
    const int*   lab = (const int*)d_in[7];
    float* out = (float*)d_out;

    const int M = out_size / (3 * D_OUT);
    const int SMEM_TOTAL = 49152 * STAGES + 1024 + 32;   // 99360

    cudaFuncSetAttribute(k_gemm, cudaFuncAttributeMaxDynamicSharedMemorySize, SMEM_TOTAL);

    k_wt<<<dim3(D_FEAT / 32, NTOT / 32), dim3(32, 8)>>>(Wa, Ws, Wc);
    k_zero<<<1, 64>>>();
    k_hist<<<N_REL / 256, 256>>>(lab);
    k_scan<<<1, 32>>>();
    k_rank<<<N_CLS, 256>>>(lab);
    k_pairs<<<N_REL / 256, 256>>>(lab);
    k_diff<<<M, 256>>>(X);

    dim3 grid(NTOT / TN, N_REL / TM);   // (6, 512)
    k_gemm<<<grid, 256, SMEM_TOTAL>>>(Wa, Ws, Wc, ba, bs, bc, out, M);
}

// round 4
// speedup vs baseline: 5.7720x; 1.3195x over previous
#include <cuda_runtime.h>
#include <cuda_bf16.h>
#include <cstdint>

#define N_REL   65536
#define D_FEAT  3872
#define D_OUT   512
#define N_CLS   36
#define NTOT    1536            // 3 heads * 512
#define KCHUNK  32              // floats per K tile (128 bytes)
#define NK      (D_FEAT / KCHUNK)   // 121
#define TM      128
#define TN      256
#define STAGES  4
#define STAGE_BYTES 49152       // A 16KB + B 32KB

#if defined(__CUDA_ARCH_FEAT_SM103_ALL) || defined(__CUDA_ARCH_FEAT_SM100_ALL) || defined(__CUDA_ARCH_FEAT_SM101_ALL)
#define HAS_TCGEN05 1
#else
#define HAS_TCGEN05 0
#endif

// ---------------- device scratch ----------------
__device__ int g_cnt[N_CLS];
__device__ int g_off[N_CLS + 1];
__device__ int g_poff[N_CLS];
__device__ int g_sorted[N_REL];
__device__ int g_lo[N_REL];
__device__ int g_hi[N_REL];
__device__ float g_wt[(size_t)NTOT * D_FEAT];          // 24 MB, K-major weights
__device__ float g_diff[(size_t)N_REL * D_FEAT];       // ~1.01 GB

// ---------------- PTX helpers ----------------
__device__ __forceinline__ uint32_t smem_to_u32(const void* p) {
    uint32_t a;
    asm("{ .reg .u64 t; cvta.to.shared.u64 t, %1; cvt.u32.u64 %0, t; }" : "=r"(a) : "l"(p));
    return a;
}
#define MBARRIER_INIT(mbar, cnt) \
    asm volatile("mbarrier.init.shared.b64 [%0], %1;" :: "r"((uint32_t)(mbar)), "r"((uint32_t)(cnt)) : "memory")
#define MBARRIER_ARRIVE(mbar) \
    asm volatile("mbarrier.arrive.shared.b64 _, [%0];" :: "r"((uint32_t)(mbar)) : "memory")
#define MBARRIER_WAIT_PARITY(mbar, par) do {                                        \
    uint32_t _m = (uint32_t)(mbar); uint32_t _p = (uint32_t)(par); uint32_t _d;     \
    asm volatile("{\n\t.reg .pred p;\n\t"                                           \
        "mbarrier.try_wait.parity.acquire.cta.shared::cta.b64 p, [%1], %2;\n\t"     \
        "selp.b32 %0, 1, 0, p;\n\t}" : "=r"(_d) : "r"(_m), "r"(_p) : "memory");     \
    if (!_d) {                                                                      \
        asm volatile("{\n\t.reg .pred P1;\n\t"                                      \
        "WL_%=:\n\tmbarrier.try_wait.parity.acquire.cta.shared::cta.b64 P1, [%0], %1, 0x989680;\n\t" \
        "@P1 bra.uni WD_%=;\n\tbra.uni WL_%=;\n\tWD_%=:\n\t}"                       \
        :: "r"(_m), "r"(_p) : "memory");                                            \
    } } while (0)
#define SMEM_SWIZZLE_128B(o)   ((o) ^ (((o) >> 3) & 0x70))
#define FENCE_ASYNC_SHARED()   asm volatile("fence.proxy.async.shared::cta;" ::: "memory")

#if HAS_TCGEN05
__device__ __forceinline__ uint32_t elect_one_pred() {
    uint32_t pred;
    asm volatile("{\n\t.reg .pred p;\n\telect.sync _|p, 0xFFFFFFFF;\n\tselp.b32 %0, 1, 0, p;\n\t}"
                 : "=r"(pred));
    return pred;
}
#define TCGEN05_ALLOC(sr, nc) \
    asm volatile("tcgen05.alloc.cta_group::1.sync.aligned.shared::cta.b32 [%0], %1;" \
                 :: "r"((uint32_t)(sr)), "r"((uint32_t)(nc)) : "memory")
#define TCGEN05_DEALLOC(t, nc) \
    asm volatile("tcgen05.dealloc.cta_group::1.sync.aligned.b32 %0, %1;" :: "r"(t), "r"((uint32_t)(nc)))
#define TCGEN05_RELINQ() \
    asm volatile("tcgen05.relinquish_alloc_permit.cta_group::1.sync.aligned;")
#define TCGEN05_COMMIT(mbar) \
    asm volatile("tcgen05.commit.cta_group::1.mbarrier::arrive::one.shared::cluster.b64 [%0];" \
                 :: "r"((uint32_t)(mbar)) : "memory")
#define TCGEN05_FENCE_AFTER()  asm volatile("tcgen05.fence::after_thread_sync;" ::: "memory")
#define TCGEN05_FENCE_BEFORE() asm volatile("tcgen05.fence::before_thread_sync;" ::: "memory")
#define TCGEN05_WAIT_LD()      asm volatile("tcgen05.wait::ld.sync.aligned;" ::: "memory")
#define TCGEN05_LD_X32(r, ta) \
    asm volatile("tcgen05.ld.sync.aligned.32x32b.x32.b32 " \
        "{%0,%1,%2,%3,%4,%5,%6,%7,%8,%9,%10,%11,%12,%13,%14,%15," \
        "%16,%17,%18,%19,%20,%21,%22,%23,%24,%25,%26,%27,%28,%29,%30,%31}, [%32];" \
        : "=r"((r)[0]),"=r"((r)[1]),"=r"((r)[2]),"=r"((r)[3]),"=r"((r)[4]),"=r"((r)[5]),"=r"((r)[6]),"=r"((r)[7]), \
          "=r"((r)[8]),"=r"((r)[9]),"=r"((r)[10]),"=r"((r)[11]),"=r"((r)[12]),"=r"((r)[13]),"=r"((r)[14]),"=r"((r)[15]), \
          "=r"((r)[16]),"=r"((r)[17]),"=r"((r)[18]),"=r"((r)[19]),"=r"((r)[20]),"=r"((r)[21]),"=r"((r)[22]),"=r"((r)[23]), \
          "=r"((r)[24]),"=r"((r)[25]),"=r"((r)[26]),"=r"((r)[27]),"=r"((r)[28]),"=r"((r)[29]),"=r"((r)[30]),"=r"((r)[31]) \
        : "r"(ta))

static constexpr uint64_t SMEM_DESC_BASE_SW128 =
    (uint64_t(2) << 61) | (uint64_t(1) << 46) | (uint64_t(64) << 32) | (uint64_t(1) << 16);
__device__ __forceinline__ uint64_t make_desc(uint32_t addr) {
    return SMEM_DESC_BASE_SW128 | ((uint64_t)(addr >> 4) & 0x3FFF);
}
__device__ __forceinline__ void mma_tf32_ss(uint32_t d, uint64_t a, uint64_t b,
                                            uint32_t idesc, uint32_t en) {
    asm volatile("{\n\t.reg .pred p;\n\tsetp.ne.u32 p, %5, 0;\n\t"
        "tcgen05.mma.cta_group::1.kind::tf32 [%0], %1, %2, %3, {%4, %4, %4, %4}, p;\n\t}"
        :: "r"(d), "l"(a), "l"(b), "r"(idesc), "r"(0u), "r"(en) : "memory");
}
static constexpr uint32_t IDESC = (1u << 4) | (2u << 7) | (2u << 10) |
                                  ((TN / 8) << 17) | ((TM / 16) << 24);
#endif  // HAS_TCGEN05

// ---------------- index construction ----------------
__global__ void k_zero() { if (threadIdx.x < N_CLS) g_cnt[threadIdx.x] = 0; }

__global__ void k_hist(const int* __restrict__ lab) {
    int i = blockIdx.x * blockDim.x + threadIdx.x;
    if (i < N_REL) atomicAdd(&g_cnt[lab[i]], 1);
}
__global__ void k_scan() {
    if (threadIdx.x == 0) {
        int run = 0, prun = 0;
        g_off[0] = 0;
        for (int c = 0; c < N_CLS; c++) {
            g_poff[c] = prun;
            int cnt = g_cnt[c];
            run += cnt; g_off[c + 1] = run;
            prun += (cnt > 0) ? (cnt - 1) : 0;
        }
    }
}
__global__ void k_rank(const int* __restrict__ lab) {
    const int c = blockIdx.x, tid = threadIdx.x;
    __shared__ int wsum[8];
    const int base_off = g_off[c];
    int sbase = 0;
    for (int start = 0; start < N_REL; start += 256) {
        int i = start + tid;
        int flag = (lab[i] == c) ? 1 : 0;
        unsigned mask = __ballot_sync(0xffffffffu, flag);
        if ((tid & 31) == 0) wsum[tid >> 5] = __popc(mask);
        __syncthreads();
        int wbase = 0, total = 0, wi = tid >> 5;
        #pragma unroll
        for (int j = 0; j < 8; j++) { int v = wsum[j]; total += v; if (j < wi) wbase += v; }
        if (flag) {
            int excl = __popc(mask & ((1u << (tid & 31)) - 1u));
            g_sorted[base_off + sbase + wbase + excl] = i;
        }
        sbase += total;
        __syncthreads();
    }
}
__global__ void k_pairs(const int* __restrict__ lab) {
    int p = blockIdx.x * blockDim.x + threadIdx.x;
    if (p >= N_REL) return;
    int io = g_sorted[p];
    int c = lab[io];
    if (p + 1 < g_off[c + 1]) {
        int m = p - g_off[c] + g_poff[c];
        g_lo[m] = io; g_hi[m] = g_sorted[p + 1];
    }
}

// ---------------- materialize diff rows ----------------
__global__ void k_diff(const float* __restrict__ X) {
    int m = blockIdx.x;
    int lo = g_lo[m], hi = g_hi[m];
    const float4* rl = (const float4*)(X + (size_t)lo * D_FEAT);
    const float4* rh = (const float4*)(X + (size_t)hi * D_FEAT);
    float4* dst = (float4*)(g_diff + (size_t)m * D_FEAT);
    for (int q = threadIdx.x; q < D_FEAT / 4; q += 256) {
        float4 a = rh[q], b = rl[q];
        float4 d; d.x = a.x - b.x; d.y = a.y - b.y; d.z = a.z - b.z; d.w = a.w - b.w;
        dst[q] = d;
    }
}

// ---------------- transpose weights to K-major ----------------
__global__ void k_wt(const float* __restrict__ Wa, const float* __restrict__ Ws,
                     const float* __restrict__ Wc) {
    __shared__ float tile[32][33];
    int kb = blockIdx.x * 32;
    int ng = blockIdx.y;
    int head = ng >> 4;
    const float* W = (head == 0) ? Wa : ((head == 1) ? Ws : Wc);
    int nb = (ng & 15) * 32;
    int tx = threadIdx.x, ty = threadIdx.y;  // (32, 8)
    #pragma unroll
    for (int r = 0; r < 4; r++) {
        int k = kb + ty + r * 8;
        tile[ty + r * 8][tx] = W[(size_t)k * D_OUT + nb + tx];
    }
    __syncthreads();
    #pragma unroll
    for (int r = 0; r < 4; r++) {
        int n = ng * 32 + ty + r * 8;
        g_wt[(size_t)n * D_FEAT + kb + tx] = tile[tx][ty + r * 8];
    }
}

// ---------------- GEMM: out = diff @ Wt^T + bias ----------------
// grid: x = 6 N-tiles (256 cols), y = 512 M-tiles (128 rows); 256 threads.
__global__ __launch_bounds__(256, 1)
void k_gemm(const float* __restrict__ Wa, const float* __restrict__ Ws,
            const float* __restrict__ Wc,
            const float* __restrict__ ba, const float* __restrict__ bs,
            const float* __restrict__ bc, float* __restrict__ out, int M) {
    extern __shared__ char smem[];
#if HAS_TCGEN05
    // ======================= tcgen05 tf32 path =======================
    const uint32_t sb = smem_to_u32(smem);
    // layout: [0..4) tmem ptr | [8..40) full[4] | [40..72) empty[4] | data @1024-aligned
    const uint32_t full0  = sb + 8;
    const uint32_t empty0 = sb + 40;
    const uint32_t data = (sb + 72 + 1023) & ~1023u;
    char* datap = smem + (data - sb);

    const int tid = threadIdx.x;
    const int wid = tid >> 5;
    const int lid = tid & 31;
    const int m0 = blockIdx.y * TM;
    const int n0 = blockIdx.x * TN;

    if (wid == 0) TCGEN05_ALLOC(sb, 256);
    if (tid == 0) {
        #pragma unroll
        for (int s = 0; s < STAGES; s++) {
            MBARRIER_INIT(full0 + s * 8, 256);   // all threads arrive
            MBARRIER_INIT(empty0 + s * 8, 1);    // tcgen05 commit arrives
        }
    }
    __syncthreads();
    uint32_t tmem;
    asm volatile("ld.shared.b32 %0, [%1];" : "=r"(tmem) : "r"(sb));

    const float* __restrict__ Asrc = g_diff + (size_t)m0 * D_FEAT;
    const float* __restrict__ Bsrc = g_wt + (size_t)n0 * D_FEAT;

    const bool issuer = (wid == 0) && elect_one_pred();

    for (int i = 0; i < NK; i++) {
        const int s = i & (STAGES - 1);
        const uint32_t A_base = data + (uint32_t)s * STAGE_BYTES;
        const uint32_t B_base = A_base + 16384u;

        // producer: wait for buffer s free (MMA of chunk i-STAGES committed)
        if (i >= STAGES) {
            MBARRIER_WAIT_PARITY(empty0 + s * 8, ((i >> 2) - 1) & 1);
        }
        const int k0 = i * KCHUNK;
        {   // A tile: 128 rows x 32 floats (4 float4/thread)
            char* As = datap + (A_base - data);
            #pragma unroll
            for (int j = 0; j < 4; j++) {
                int e = j * 256 + tid;
                int row = e >> 3, q = e & 7;
                float4 v = *(const float4*)(Asrc + (size_t)row * D_FEAT + k0 + q * 4);
                uint32_t off = SMEM_SWIZZLE_128B((uint32_t)(row * 128 + q * 16));
                *(float4*)(As + off) = v;
            }
        }
        {   // B tile: 256 rows x 32 floats (8 float4/thread)
            char* Bs = datap + (B_base - data);
            #pragma unroll
            for (int j = 0; j < 8; j++) {
                int e = j * 256 + tid;
                int row = e >> 3, q = e & 7;
                float4 v = *(const float4*)(Bsrc + (size_t)row * D_FEAT + k0 + q * 4);
                uint32_t off = SMEM_SWIZZLE_128B((uint32_t)(row * 128 + q * 16));
                *(float4*)(Bs + off) = v;
            }
        }
        FENCE_ASYNC_SHARED();
        MBARRIER_ARRIVE(full0 + s * 8);

        // consumer: elected lane issues MMAs for this chunk
        if (issuer) {
            MBARRIER_WAIT_PARITY(full0 + s * 8, (i >> 2) & 1);
            uint64_t ad = make_desc(A_base);
            uint64_t bd = make_desc(B_base);
            #pragma unroll
            for (int ks = 0; ks < 4; ks++) {
                mma_tf32_ss(tmem, ad + ks * 2, bd + ks * 2, IDESC,
                            (i > 0 || ks > 0) ? 1u : 0u);
            }
            TCGEN05_COMMIT(empty0 + s * 8);
        }
    }
    // all threads wait for the final chunk's commit (i=120, s=0, parity (120>>2)&1 = 0)
    MBARRIER_WAIT_PARITY(empty0 + ((NK - 1) & (STAGES - 1)) * 8, ((NK - 1) >> 2) & 1);
    TCGEN05_FENCE_AFTER();

    const int head = n0 / D_OUT;
    const int ncl = n0 % D_OUT;
    const float* __restrict__ bias = (head == 0) ? ba : ((head == 1) ? bs : bc);
    const int wcol = (wid >= 4) ? 128 : 0;
    const int m = m0 + (wid & 3) * 32 + lid;

    #pragma unroll
    for (int cc = 0; cc < 128; cc += 32) {
        uint32_t r[32];
        TCGEN05_LD_X32(r, tmem + wcol + cc);
        TCGEN05_WAIT_LD();
        if (m < M) {
            int col = ncl + wcol + cc;
            float* dst = out + ((size_t)head * M + m) * D_OUT + col;
            #pragma unroll
            for (int q = 0; q < 8; q++) {
                float4 o;
                o.x = __uint_as_float(r[q * 4 + 0]) + bias[col + q * 4 + 0];
                o.y = __uint_as_float(r[q * 4 + 1]) + bias[col + q * 4 + 1];
                o.z = __uint_as_float(r[q * 4 + 2]) + bias[col + q * 4 + 2];
                o.w = __uint_as_float(r[q * 4 + 3]) + bias[col + q * 4 + 3];
                *(float4*)(dst + q * 4) = o;
            }
        }
    }
    TCGEN05_FENCE_BEFORE();
    __syncthreads();
    if (wid == 0) {
        TCGEN05_RELINQ();
        TCGEN05_DEALLOC(tmem, 256);
    }
#else
    // ======================= SIMT fallback (compute_103 pass) =======================
    float (*As)[128] = (float(*)[128])smem;                       // [16][128]
    float (*Bs)[128] = (float(*)[128])(smem + 16 * 128 * 4);      // [16][128]
    const int tid = threadIdx.x;
    const int tx = tid & 15;
    const int ty = tid >> 4;
    const int m0 = blockIdx.y * TM;

    for (int h = 0; h < 2; h++) {
        const int n0 = blockIdx.x * TN + h * 128;
        const int head = n0 / D_OUT;
        const int ncl = n0 % D_OUT;
        const float* __restrict__ W    = (head == 0) ? Wa : ((head == 1) ? Ws : Wc);
        const float* __restrict__ bias = (head == 0) ? ba : ((head == 1) ? bs : bc);

        float acc[8][8];
        #pragma unroll
        for (int i = 0; i < 8; i++)
            #pragma unroll
            for (int j = 0; j < 8; j++) acc[i][j] = 0.0f;

        for (int k0 = 0; k0 < D_FEAT; k0 += 16) {
            #pragma unroll
            for (int jj = 0; jj < 2; jj++) {
                int idx = tid * 2 + jj;
                int row = idx >> 2, kq = idx & 3;
                float4 v = *(const float4*)(g_diff + (size_t)(m0 + row) * D_FEAT + k0 + kq * 4);
                As[kq * 4 + 0][row] = v.x; As[kq * 4 + 1][row] = v.y;
                As[kq * 4 + 2][row] = v.z; As[kq * 4 + 3][row] = v.w;
            }
            #pragma unroll
            for (int jj = 0; jj < 2; jj++) {
                int l = tid * 2 + jj;
                int k = l >> 5, nq = l & 31;
                *(float4*)&Bs[k][nq * 4] =
                    *(const float4*)(W + (size_t)(k0 + k) * D_OUT + ncl + nq * 4);
            }
            __syncthreads();
            #pragma unroll
            for (int k = 0; k < 16; k++) {
                float4 a0 = *(const float4*)&As[k][ty * 8];
                float4 a1 = *(const float4*)&As[k][ty * 8 + 4];
                float4 b0 = *(const float4*)&Bs[k][tx * 8];
                float4 b1 = *(const float4*)&Bs[k][tx * 8 + 4];
                float av[8] = {a0.x, a0.y, a0.z, a0.w, a1.x, a1.y, a1.z, a1.w};
                float bv[8] = {b0.x, b0.y, b0.z, b0.w, b1.x, b1.y, b1.z, b1.w};
                #pragma unroll
                for (int i = 0; i < 8; i++)
                    #pragma unroll
                    for (int j = 0; j < 8; j++)
                        acc[i][j] = fmaf(av[i], bv[j], acc[i][j]);
            }
            __syncthreads();
        }

        float bv[8];
        #pragma unroll
        for (int j = 0; j < 8; j++) bv[j] = bias[ncl + tx * 8 + j];
        #pragma unroll
        for (int i = 0; i < 8; i++) {
            int gm = m0 + ty * 8 + i;
            if (gm < M) {
                float* dst = out + ((size_t)head * M + gm) * D_OUT + ncl + tx * 8;
                float4 o0, o1;
                o0.x = acc[i][0] + bv[0]; o0.y = acc[i][1] + bv[1];
                o0.z = acc[i][2] + bv[2]; o0.w = acc[i][3] + bv[3];
                o1.x = acc[i][4] + bv[4]; o1.y = acc[i][5] + bv[5];
                o1.z = acc[i][6] + bv[6]; o1.w = acc[i][7] + bv[7];
                *(float4*)(dst)     = o0;
                *(float4*)(dst + 4) = o1;
            }
        }
        __syncthreads();
    }
#endif
}

// ---------------- launch ----------------
extern "C" void kernel_launch(void* const* d_in, const int* in_sizes, int n_in,
                              void* d_out, int out_size) {
    const float* X   = (const float*)d_in[0];
    const float* Wa  = (const float*)d_in[1];
    const float* ba  = (const float*)d_in[2];
    const float* Ws  = (const float*)d_in[3];
    const float* bs  = (const float*)d_in[4];
    const float* Wc  = (const float*)d_in[5];
    const float* bc  = (const float*)d_in[6];
    const int*   lab = (const int*)d_in[7];
    float* out = (float*)d_out;

    const int M = out_size / (3 * D_OUT);
    const int SMEM_TOTAL = STAGE_BYTES * STAGES + 1024 + 128;   // 197760

    cudaFuncSetAttribute(k_gemm, cudaFuncAttributeMaxDynamicSharedMemorySize, SMEM_TOTAL);

    k_wt<<<dim3(D_FEAT / 32, NTOT / 32), dim3(32, 8)>>>(Wa, Ws, Wc);
    k_zero<<<1, 64>>>();
    k_hist<<<N_REL / 256, 256>>>(lab);
    k_scan<<<1, 32>>>();
    k_rank<<<N_CLS, 256>>>(lab);
    k_pairs<<<N_REL / 256, 256>>>(lab);
    k_diff<<<M, 256>>>(X);

    dim3 grid(NTOT / TN, N_REL / TM);   // (6, 512)
    k_gemm<<<grid, 256, SMEM_TOTAL>>>(Wa, Ws, Wc, ba, bs, bc, out, M);
}

// round 5
// speedup vs baseline: 8.0148x; 1.3886x over previous
#include <cuda_runtime.h>
#include <cuda_bf16.h>
#include <cstdint>

#define N_REL   65536
#define D_FEAT  3872
#define D_OUT   512
#define N_CLS   36
#define NTOT    1536            // 3 heads * 512
#define KCHUNK  32              // floats per K tile (128 bytes)
#define NK      (D_FEAT / KCHUNK)   // 121
#define TM      256             // per-CTA M (2 x 128-row MMAs)
#define TN      256
#define STAGES  3
#define STAGE_BYTES 65536       // A 32KB + B 32KB

#if defined(__CUDA_ARCH_FEAT_SM103_ALL) || defined(__CUDA_ARCH_FEAT_SM100_ALL) || defined(__CUDA_ARCH_FEAT_SM101_ALL)
#define HAS_TCGEN05 1
#else
#define HAS_TCGEN05 0
#endif

// ---------------- device scratch ----------------
__device__ int g_cnt[N_CLS];
__device__ int g_off[N_CLS + 1];
__device__ int g_poff[N_CLS];
__device__ int g_sorted[N_REL];
__device__ int g_lo[N_REL];
__device__ int g_hi[N_REL];
__device__ float g_wt[(size_t)NTOT * D_FEAT];          // 24 MB, K-major weights
__device__ float g_diff[(size_t)N_REL * D_FEAT];       // ~1.01 GB

// ---------------- PTX helpers ----------------
__device__ __forceinline__ uint32_t smem_to_u32(const void* p) {
    uint32_t a;
    asm("{ .reg .u64 t; cvta.to.shared.u64 t, %1; cvt.u32.u64 %0, t; }" : "=r"(a) : "l"(p));
    return a;
}
#define MBARRIER_INIT(mbar, cnt) \
    asm volatile("mbarrier.init.shared.b64 [%0], %1;" :: "r"((uint32_t)(mbar)), "r"((uint32_t)(cnt)) : "memory")
#define MBARRIER_ARRIVE(mbar) \
    asm volatile("mbarrier.arrive.shared.b64 _, [%0];" :: "r"((uint32_t)(mbar)) : "memory")
#define MBARRIER_WAIT_PARITY(mbar, par) do {                                        \
    uint32_t _m = (uint32_t)(mbar); uint32_t _p = (uint32_t)(par); uint32_t _d;     \
    asm volatile("{\n\t.reg .pred p;\n\t"                                           \
        "mbarrier.try_wait.parity.acquire.cta.shared::cta.b64 p, [%1], %2;\n\t"     \
        "selp.b32 %0, 1, 0, p;\n\t}" : "=r"(_d) : "r"(_m), "r"(_p) : "memory");     \
    if (!_d) {                                                                      \
        asm volatile("{\n\t.reg .pred P1;\n\t"                                      \
        "WL_%=:\n\tmbarrier.try_wait.parity.acquire.cta.shared::cta.b64 P1, [%0], %1, 0x989680;\n\t" \
        "@P1 bra.uni WD_%=;\n\tbra.uni WL_%=;\n\tWD_%=:\n\t}"                       \
        :: "r"(_m), "r"(_p) : "memory");                                            \
    } } while (0)
#define SMEM_SWIZZLE_128B(o)   ((o) ^ (((o) >> 3) & 0x70))
#define FENCE_ASYNC_SHARED()   asm volatile("fence.proxy.async.shared::cta;" ::: "memory")

#if HAS_TCGEN05
__device__ __forceinline__ uint32_t elect_one_pred() {
    uint32_t pred;
    asm volatile("{\n\t.reg .pred p;\n\telect.sync _|p, 0xFFFFFFFF;\n\tselp.b32 %0, 1, 0, p;\n\t}"
                 : "=r"(pred));
    return pred;
}
#define TCGEN05_ALLOC(sr, nc) \
    asm volatile("tcgen05.alloc.cta_group::1.sync.aligned.shared::cta.b32 [%0], %1;" \
                 :: "r"((uint32_t)(sr)), "r"((uint32_t)(nc)) : "memory")
#define TCGEN05_DEALLOC(t, nc) \
    asm volatile("tcgen05.dealloc.cta_group::1.sync.aligned.b32 %0, %1;" :: "r"(t), "r"((uint32_t)(nc)))
#define TCGEN05_RELINQ() \
    asm volatile("tcgen05.relinquish_alloc_permit.cta_group::1.sync.aligned;")
#define TCGEN05_COMMIT(mbar) \
    asm volatile("tcgen05.commit.cta_group::1.mbarrier::arrive::one.shared::cluster.b64 [%0];" \
                 :: "r"((uint32_t)(mbar)) : "memory")
#define TCGEN05_FENCE_AFTER()  asm volatile("tcgen05.fence::after_thread_sync;" ::: "memory")
#define TCGEN05_FENCE_BEFORE() asm volatile("tcgen05.fence::before_thread_sync;" ::: "memory")
#define TCGEN05_WAIT_LD()      asm volatile("tcgen05.wait::ld.sync.aligned;" ::: "memory")
#define TCGEN05_LD_X32(r, ta) \
    asm volatile("tcgen05.ld.sync.aligned.32x32b.x32.b32 " \
        "{%0,%1,%2,%3,%4,%5,%6,%7,%8,%9,%10,%11,%12,%13,%14,%15," \
        "%16,%17,%18,%19,%20,%21,%22,%23,%24,%25,%26,%27,%28,%29,%30,%31}, [%32];" \
        : "=r"((r)[0]),"=r"((r)[1]),"=r"((r)[2]),"=r"((r)[3]),"=r"((r)[4]),"=r"((r)[5]),"=r"((r)[6]),"=r"((r)[7]), \
          "=r"((r)[8]),"=r"((r)[9]),"=r"((r)[10]),"=r"((r)[11]),"=r"((r)[12]),"=r"((r)[13]),"=r"((r)[14]),"=r"((r)[15]), \
          "=r"((r)[16]),"=r"((r)[17]),"=r"((r)[18]),"=r"((r)[19]),"=r"((r)[20]),"=r"((r)[21]),"=r"((r)[22]),"=r"((r)[23]), \
          "=r"((r)[24]),"=r"((r)[25]),"=r"((r)[26]),"=r"((r)[27]),"=r"((r)[28]),"=r"((r)[29]),"=r"((r)[30]),"=r"((r)[31]) \
        : "r"(ta))

static constexpr uint64_t SMEM_DESC_BASE_SW128 =
    (uint64_t(2) << 61) | (uint64_t(1) << 46) | (uint64_t(64) << 32) | (uint64_t(1) << 16);
__device__ __forceinline__ uint64_t make_desc(uint32_t addr) {
    return SMEM_DESC_BASE_SW128 | ((uint64_t)(addr >> 4) & 0x3FFF);
}
__device__ __forceinline__ void mma_tf32_ss(uint32_t d, uint64_t a, uint64_t b,
                                            uint32_t idesc, uint32_t en) {
    asm volatile("{\n\t.reg .pred p;\n\tsetp.ne.u32 p, %5, 0;\n\t"
        "tcgen05.mma.cta_group::1.kind::tf32 [%0], %1, %2, %3, {%4, %4, %4, %4}, p;\n\t}"
        :: "r"(d), "l"(a), "l"(b), "r"(idesc), "r"(0u), "r"(en) : "memory");
}
// dtype=f32 | atype=tf32 | btype=tf32 | N=256 | M=128
static constexpr uint32_t IDESC = (1u << 4) | (2u << 7) | (2u << 10) |
                                  ((TN / 8) << 17) | ((128 / 16) << 24);
#endif  // HAS_TCGEN05

// ---------------- index construction ----------------
__global__ void k_zero() { if (threadIdx.x < N_CLS) g_cnt[threadIdx.x] = 0; }

__global__ void k_hist(const int* __restrict__ lab) {
    int i = blockIdx.x * blockDim.x + threadIdx.x;
    if (i < N_REL) atomicAdd(&g_cnt[lab[i]], 1);
}
__global__ void k_scan() {
    if (threadIdx.x == 0) {
        int run = 0, prun = 0;
        g_off[0] = 0;
        for (int c = 0; c < N_CLS; c++) {
            g_poff[c] = prun;
            int cnt = g_cnt[c];
            run += cnt; g_off[c + 1] = run;
            prun += (cnt > 0) ? (cnt - 1) : 0;
        }
    }
}
__global__ void k_rank(const int* __restrict__ lab) {
    const int c = blockIdx.x, tid = threadIdx.x;
    __shared__ int wsum[8];
    const int base_off = g_off[c];
    int sbase = 0;
    for (int start = 0; start < N_REL; start += 256) {
        int i = start + tid;
        int flag = (lab[i] == c) ? 1 : 0;
        unsigned mask = __ballot_sync(0xffffffffu, flag);
        if ((tid & 31) == 0) wsum[tid >> 5] = __popc(mask);
        __syncthreads();
        int wbase = 0, total = 0, wi = tid >> 5;
        #pragma unroll
        for (int j = 0; j < 8; j++) { int v = wsum[j]; total += v; if (j < wi) wbase += v; }
        if (flag) {
            int excl = __popc(mask & ((1u << (tid & 31)) - 1u));
            g_sorted[base_off + sbase + wbase + excl] = i;
        }
        sbase += total;
        __syncthreads();
    }
}
__global__ void k_pairs(const int* __restrict__ lab) {
    int p = blockIdx.x * blockDim.x + threadIdx.x;
    if (p >= N_REL) return;
    int io = g_sorted[p];
    int c = lab[io];
    if (p + 1 < g_off[c + 1]) {
        int m = p - g_off[c] + g_poff[c];
        g_lo[m] = io; g_hi[m] = g_sorted[p + 1];
    }
}

// ---------------- materialize diff rows ----------------
__global__ void k_diff(const float* __restrict__ X) {
    int m = blockIdx.x;
    int lo = g_lo[m], hi = g_hi[m];
    const float4* rl = (const float4*)(X + (size_t)lo * D_FEAT);
    const float4* rh = (const float4*)(X + (size_t)hi * D_FEAT);
    float4* dst = (float4*)(g_diff + (size_t)m * D_FEAT);
    for (int q = threadIdx.x; q < D_FEAT / 4; q += 256) {
        float4 a = rh[q], b = rl[q];
        float4 d; d.x = a.x - b.x; d.y = a.y - b.y; d.z = a.z - b.z; d.w = a.w - b.w;
        dst[q] = d;
    }
}

// ---------------- transpose weights to K-major ----------------
__global__ void k_wt(const float* __restrict__ Wa, const float* __restrict__ Ws,
                     const float* __restrict__ Wc) {
    __shared__ float tile[32][33];
    int kb = blockIdx.x * 32;
    int ng = blockIdx.y;
    int head = ng >> 4;
    const float* W = (head == 0) ? Wa : ((head == 1) ? Ws : Wc);
    int nb = (ng & 15) * 32;
    int tx = threadIdx.x, ty = threadIdx.y;  // (32, 8)
    #pragma unroll
    for (int r = 0; r < 4; r++) {
        int k = kb + ty + r * 8;
        tile[ty + r * 8][tx] = W[(size_t)k * D_OUT + nb + tx];
    }
    __syncthreads();
    #pragma unroll
    for (int r = 0; r < 4; r++) {
        int n = ng * 32 + ty + r * 8;
        g_wt[(size_t)n * D_FEAT + kb + tx] = tile[tx][ty + r * 8];
    }
}

// ---------------- GEMM: out = diff @ Wt^T + bias ----------------
// grid: x = 6 N-tiles (256 cols), y = 256 M-tiles (256 rows); 256 threads.
__global__ __launch_bounds__(256, 1)
void k_gemm(const float* __restrict__ Wa, const float* __restrict__ Ws,
            const float* __restrict__ Wc,
            const float* __restrict__ ba, const float* __restrict__ bs,
            const float* __restrict__ bc, float* __restrict__ out, int M) {
    extern __shared__ char smem[];
#if HAS_TCGEN05
    // ======================= tcgen05 tf32 path =======================
    const uint32_t sb = smem_to_u32(smem);
    // layout: [0..4) tmem ptr | [8..32) full[3] | [32..56) empty[3] | data @1024
    const uint32_t full0  = sb + 8;
    const uint32_t empty0 = sb + 32;
    const uint32_t data = (sb + 56 + 1023) & ~1023u;
    char* datap = smem + (data - sb);

    const int tid = threadIdx.x;
    const int wid = tid >> 5;
    const int lid = tid & 31;
    const int m0 = blockIdx.y * TM;
    const int n0 = blockIdx.x * TN;

    if (wid == 0) TCGEN05_ALLOC(sb, 512);
    if (tid == 0) {
        #pragma unroll
        for (int s = 0; s < STAGES; s++) {
            MBARRIER_INIT(full0 + s * 8, 256);   // all threads arrive
            MBARRIER_INIT(empty0 + s * 8, 1);    // tcgen05 commit arrives
        }
    }
    __syncthreads();
    uint32_t tmem;
    asm volatile("ld.shared.b32 %0, [%1];" : "=r"(tmem) : "r"(sb));

    const float* __restrict__ Asrc = g_diff + (size_t)m0 * D_FEAT;
    const float* __restrict__ Bsrc = g_wt + (size_t)n0 * D_FEAT;

    const bool issuer = (wid == 0) && elect_one_pred();

    int s = 0, ph = 0;   // stage and phase (i / STAGES parity tracked via ph)
    for (int i = 0; i < NK; i++) {
        const uint32_t A_base = data + (uint32_t)s * STAGE_BYTES;
        const uint32_t B_base = A_base + 32768u;

        // producer: wait for buffer s free (commit of chunk i-STAGES; index ph-1)
        if (i >= STAGES) {
            MBARRIER_WAIT_PARITY(empty0 + s * 8, (ph ^ 1) & 1);
        }
        const int k0 = i * KCHUNK;
        {   // A tile: 256 rows x 32 floats (8 float4/thread)
            char* As = datap + (A_base - data);
            #pragma unroll
            for (int j = 0; j < 8; j++) {
                int e = j * 256 + tid;
                int row = e >> 3, q = e & 7;
                float4 v = *(const float4*)(Asrc + (size_t)row * D_FEAT + k0 + q * 4);
                uint32_t off = SMEM_SWIZZLE_128B((uint32_t)(row * 128 + q * 16));
                *(float4*)(As + off) = v;
            }
        }
        {   // B tile: 256 rows x 32 floats (8 float4/thread)
            char* Bs = datap + (B_base - data);
            #pragma unroll
            for (int j = 0; j < 8; j++) {
                int e = j * 256 + tid;
                int row = e >> 3, q = e & 7;
                float4 v = *(const float4*)(Bsrc + (size_t)row * D_FEAT + k0 + q * 4);
                uint32_t off = SMEM_SWIZZLE_128B((uint32_t)(row * 128 + q * 16));
                *(float4*)(Bs + off) = v;
            }
        }
        FENCE_ASYNC_SHARED();
        MBARRIER_ARRIVE(full0 + s * 8);

        // consumer: elected lane issues 8 MMAs (2 M-halves x 4 K-steps)
        if (issuer) {
            MBARRIER_WAIT_PARITY(full0 + s * 8, ph & 1);
            uint64_t ad0 = make_desc(A_base);
            uint64_t ad1 = make_desc(A_base + 16384u);   // rows 128..255
            uint64_t bd  = make_desc(B_base);
            #pragma unroll
            for (int ks = 0; ks < 4; ks++) {
                uint32_t en = (i > 0 || ks > 0) ? 1u : 0u;
                mma_tf32_ss(tmem,        ad0 + ks * 2, bd + ks * 2, IDESC, en);
                mma_tf32_ss(tmem + 256,  ad1 + ks * 2, bd + ks * 2, IDESC, en);
            }
            TCGEN05_COMMIT(empty0 + s * 8);
        }
        if (++s == STAGES) { s = 0; ph ^= 1; }
    }
    // final wait: last chunk i=120 used stage 0, commit index 40 -> parity 0
    MBARRIER_WAIT_PARITY(empty0 + ((NK - 1) % STAGES) * 8, ((NK - 1) / STAGES) & 1);
    TCGEN05_FENCE_AFTER();

    const int head = n0 / D_OUT;
    const int ncl = n0 % D_OUT;
    const float* __restrict__ bias = (head == 0) ? ba : ((head == 1) ? bs : bc);
    // warps 0-3: D0 (rows m0+0..127, TMEM cols 0..255)
    // warps 4-7: D1 (rows m0+128..255, TMEM cols 256..511)
    const uint32_t dbase = tmem + ((wid >= 4) ? 256u : 0u);
    const int m = m0 + ((wid >= 4) ? 128 : 0) + (wid & 3) * 32 + lid;

    #pragma unroll
    for (int cc = 0; cc < 256; cc += 32) {
        uint32_t r[32];
        TCGEN05_LD_X32(r, dbase + cc);
        TCGEN05_WAIT_LD();
        if (m < M) {
            int col = ncl + cc;
            float* dst = out + ((size_t)head * M + m) * D_OUT + col;
            #pragma unroll
            for (int q = 0; q < 8; q++) {
                float4 o;
                o.x = __uint_as_float(r[q * 4 + 0]) + bias[col + q * 4 + 0];
                o.y = __uint_as_float(r[q * 4 + 1]) + bias[col + q * 4 + 1];
                o.z = __uint_as_float(r[q * 4 + 2]) + bias[col + q * 4 + 2];
                o.w = __uint_as_float(r[q * 4 + 3]) + bias[col + q * 4 + 3];
                *(float4*)(dst + q * 4) = o;
            }
        }
    }
    TCGEN05_FENCE_BEFORE();
    __syncthreads();
    if (wid == 0) {
        TCGEN05_RELINQ();
        TCGEN05_DEALLOC(tmem, 512);
    }
#else
    // ======================= SIMT fallback (compute_103 pass) =======================
    float (*As)[128] = (float(*)[128])smem;                       // [16][128]
    float (*Bs)[128] = (float(*)[128])(smem + 16 * 128 * 4);      // [16][128]
    const int tid = threadIdx.x;
    const int tx = tid & 15;
    const int ty = tid >> 4;

    for (int mh = 0; mh < 2; mh++) {
        const int m0 = blockIdx.y * TM + mh * 128;
        for (int h = 0; h < 2; h++) {
            const int n0 = blockIdx.x * TN + h * 128;
            const int head = n0 / D_OUT;
            const int ncl = n0 % D_OUT;
            const float* __restrict__ W    = (head == 0) ? Wa : ((head == 1) ? Ws : Wc);
            const float* __restrict__ bias = (head == 0) ? ba : ((head == 1) ? bs : bc);

            float acc[8][8];
            #pragma unroll
            for (int i = 0; i < 8; i++)
                #pragma unroll
                for (int j = 0; j < 8; j++) acc[i][j] = 0.0f;

            for (int k0 = 0; k0 < D_FEAT; k0 += 16) {
                #pragma unroll
                for (int jj = 0; jj < 2; jj++) {
                    int idx = tid * 2 + jj;
                    int row = idx >> 2, kq = idx & 3;
                    float4 v = *(const float4*)(g_diff + (size_t)(m0 + row) * D_FEAT + k0 + kq * 4);
                    As[kq * 4 + 0][row] = v.x; As[kq * 4 + 1][row] = v.y;
                    As[kq * 4 + 2][row] = v.z; As[kq * 4 + 3][row] = v.w;
                }
                #pragma unroll
                for (int jj = 0; jj < 2; jj++) {
                    int l = tid * 2 + jj;
                    int k = l >> 5, nq = l & 31;
                    *(float4*)&Bs[k][nq * 4] =
                        *(const float4*)(W + (size_t)(k0 + k) * D_OUT + ncl + nq * 4);
                }
                __syncthreads();
                #pragma unroll
                for (int k = 0; k < 16; k++) {
                    float4 a0 = *(const float4*)&As[k][ty * 8];
                    float4 a1 = *(const float4*)&As[k][ty * 8 + 4];
                    float4 b0 = *(const float4*)&Bs[k][tx * 8];
                    float4 b1 = *(const float4*)&Bs[k][tx * 8 + 4];
                    float av[8] = {a0.x, a0.y, a0.z, a0.w, a1.x, a1.y, a1.z, a1.w};
                    float bv[8] = {b0.x, b0.y, b0.z, b0.w, b1.x, b1.y, b1.z, b1.w};
                    #pragma unroll
                    for (int i = 0; i < 8; i++)
                        #pragma unroll
                        for (int j = 0; j < 8; j++)
                            acc[i][j] = fmaf(av[i], bv[j], acc[i][j]);
                }
                __syncthreads();
            }

            float bv[8];
            #pragma unroll
            for (int j = 0; j < 8; j++) bv[j] = bias[ncl + tx * 8 + j];
            #pragma unroll
            for (int i = 0; i < 8; i++) {
                int gm = m0 + ty * 8 + i;
                if (gm < M) {
                    float* dst = out + ((size_t)head * M + gm) * D_OUT + ncl + tx * 8;
                    float4 o0, o1;
                    o0.x = acc[i][0] + bv[0]; o0.y = acc[i][1] + bv[1];
                    o0.z = acc[i][2] + bv[2]; o0.w = acc[i][3] + bv[3];
                    o1.x = acc[i][4] + bv[4]; o1.y = acc[i][5] + bv[5];
                    o1.z = acc[i][6] + bv[6]; o1.w = acc[i][7] + bv[7];
                    *(float4*)(dst)     = o0;
                    *(float4*)(dst + 4) = o1;
                }
            }
            __syncthreads();
        }
    }
#endif
}

// ---------------- launch ----------------
extern "C" void kernel_launch(void* const* d_in, const int* in_sizes, int n_in,
                              void* d_out, int out_size) {
    const float* X   = (const float*)d_in[0];
    const float* Wa  = (const float*)d_in[1];
    const float* ba  = (const float*)d_in[2];
    const float* Ws  = (const float*)d_in[3];
    const float* bs  = (const float*)d_in[4];
    const float* Wc  = (const float*)d_in[5];
    const float* bc  = (const float*)d_in[6];
    const int*   lab = (const int*)d_in[7];
    float* out = (float*)d_out;

    const int M = out_size / (3 * D_OUT);
    const int SMEM_TOTAL = STAGE_BYTES * STAGES + 1024 + 128;   // ~197.8 KB

    cudaFuncSetAttribute(k_gemm, cudaFuncAttributeMaxDynamicSharedMemorySize, SMEM_TOTAL);

    k_wt<<<dim3(D_FEAT / 32, NTOT / 32), dim3(32, 8)>>>(Wa, Ws, Wc);
    k_zero<<<1, 64>>>();
    k_hist<<<N_REL / 256, 256>>>(lab);
    k_scan<<<1, 32>>>();
    k_rank<<<N_CLS, 256>>>(lab);
    k_pairs<<<N_REL / 256, 256>>>(lab);
    k_diff<<<M, 256>>>(X);

    dim3 grid(NTOT / TN, N_REL / TM);   // (6, 256)
    k_gemm<<<grid, 256, SMEM_TOTAL>>>(Wa, Ws, Wc, ba, bs, bc, out, M);
}

// round 6
// speedup vs baseline: 13.0995x; 1.6344x over previous
#include <cuda_runtime.h>
#include <cuda.h>
#include <cuda_bf16.h>
#include <cstdint>

#define N_REL   65536
#define D_FEAT  3872
#define D_OUT   512
#define N_CLS   36
#define NTOT    1536            // 3 heads * 512
#define KCHUNK  32              // floats per K tile (128 bytes)
#define NK      (D_FEAT / KCHUNK)   // 121
#define TM      256             // per-CTA M (2 x 128-row MMAs)
#define TN      256
#define STAGES  3
#define STAGE_BYTES 65536       // A 32KB + B 32KB

#if defined(__CUDA_ARCH_FEAT_SM103_ALL) || defined(__CUDA_ARCH_FEAT_SM100_ALL) || defined(__CUDA_ARCH_FEAT_SM101_ALL)
#define HAS_TCGEN05 1
#else
#define HAS_TCGEN05 0
#endif

// ---------------- device scratch ----------------
__device__ int g_cnt[N_CLS];
__device__ int g_off[N_CLS + 1];
__device__ int g_poff[N_CLS];
__device__ int g_sorted[N_REL];
__device__ int g_lo[N_REL];
__device__ int g_hi[N_REL];
__device__ float g_wt[(size_t)NTOT * D_FEAT];          // 24 MB, K-major weights
__device__ float g_y[(size_t)N_REL * NTOT];            // 402 MB, Y = X @ W (no bias)

// ---------------- PTX helpers ----------------
__device__ __forceinline__ uint32_t smem_to_u32(const void* p) {
    uint32_t a;
    asm("{ .reg .u64 t; cvta.to.shared.u64 t, %1; cvt.u32.u64 %0, t; }" : "=r"(a) : "l"(p));
    return a;
}
#define MBARRIER_INIT(mbar, cnt) \
    asm volatile("mbarrier.init.shared.b64 [%0], %1;" :: "r"((uint32_t)(mbar)), "r"((uint32_t)(cnt)) : "memory")
#define MBARRIER_EXPECT_TX(mbar, bytes) \
    asm volatile("mbarrier.arrive.expect_tx.shared.b64 _, [%0], %1;" \
                 :: "r"((uint32_t)(mbar)), "r"((uint32_t)(bytes)) : "memory")
#define MBARRIER_WAIT_PARITY(mbar, par) do {                                        \
    uint32_t _m = (uint32_t)(mbar); uint32_t _p = (uint32_t)(par); uint32_t _d;     \
    asm volatile("{\n\t.reg .pred p;\n\t"                                           \
        "mbarrier.try_wait.parity.acquire.cta.shared::cta.b64 p, [%1], %2;\n\t"     \
        "selp.b32 %0, 1, 0, p;\n\t}" : "=r"(_d) : "r"(_m), "r"(_p) : "memory");     \
    if (!_d) {                                                                      \
        asm volatile("{\n\t.reg .pred P1;\n\t"                                      \
        "WL_%=:\n\tmbarrier.try_wait.parity.acquire.cta.shared::cta.b64 P1, [%0], %1, 0x989680;\n\t" \
        "@P1 bra.uni WD_%=;\n\tbra.uni WL_%=;\n\tWD_%=:\n\t}"                       \
        :: "r"(_m), "r"(_p) : "memory");                                            \
    } } while (0)
#define SMEM_SWIZZLE_128B(o)   ((o) ^ (((o) >> 3) & 0x70))

#if HAS_TCGEN05
__device__ __forceinline__ uint32_t elect_one_pred() {
    uint32_t pred;
    asm volatile("{\n\t.reg .pred p;\n\telect.sync _|p, 0xFFFFFFFF;\n\tselp.b32 %0, 1, 0, p;\n\t}"
                 : "=r"(pred));
    return pred;
}
#define TMA_LOAD_2D(smem, tmap, cx, cy, mbar) \
    asm volatile("cp.async.bulk.tensor.2d.shared::cta.global.tile.mbarrier::complete_tx::bytes " \
                 "[%0], [%1, {%2, %3}], [%4];" \
                 :: "r"((uint32_t)(smem)), "l"(tmap), "r"((int)(cx)), "r"((int)(cy)), \
                    "r"((uint32_t)(mbar)) : "memory")
#define TCGEN05_ALLOC(sr, nc) \
    asm volatile("tcgen05.alloc.cta_group::1.sync.aligned.shared::cta.b32 [%0], %1;" \
                 :: "r"((uint32_t)(sr)), "r"((uint32_t)(nc)) : "memory")
#define TCGEN05_DEALLOC(t, nc) \
    asm volatile("tcgen05.dealloc.cta_group::1.sync.aligned.b32 %0, %1;" :: "r"(t), "r"((uint32_t)(nc)))
#define TCGEN05_RELINQ() \
    asm volatile("tcgen05.relinquish_alloc_permit.cta_group::1.sync.aligned;")
#define TCGEN05_COMMIT(mbar) \
    asm volatile("tcgen05.commit.cta_group::1.mbarrier::arrive::one.shared::cluster.b64 [%0];" \
                 :: "r"((uint32_t)(mbar)) : "memory")
#define TCGEN05_FENCE_AFTER()  asm volatile("tcgen05.fence::after_thread_sync;" ::: "memory")
#define TCGEN05_FENCE_BEFORE() asm volatile("tcgen05.fence::before_thread_sync;" ::: "memory")
#define TCGEN05_WAIT_LD()      asm volatile("tcgen05.wait::ld.sync.aligned;" ::: "memory")
#define TCGEN05_LD_X32(r, ta) \
    asm volatile("tcgen05.ld.sync.aligned.32x32b.x32.b32 " \
        "{%0,%1,%2,%3,%4,%5,%6,%7,%8,%9,%10,%11,%12,%13,%14,%15," \
        "%16,%17,%18,%19,%20,%21,%22,%23,%24,%25,%26,%27,%28,%29,%30,%31}, [%32];" \
        : "=r"((r)[0]),"=r"((r)[1]),"=r"((r)[2]),"=r"((r)[3]),"=r"((r)[4]),"=r"((r)[5]),"=r"((r)[6]),"=r"((r)[7]), \
          "=r"((r)[8]),"=r"((r)[9]),"=r"((r)[10]),"=r"((r)[11]),"=r"((r)[12]),"=r"((r)[13]),"=r"((r)[14]),"=r"((r)[15]), \
          "=r"((r)[16]),"=r"((r)[17]),"=r"((r)[18]),"=r"((r)[19]),"=r"((r)[20]),"=r"((r)[21]),"=r"((r)[22]),"=r"((r)[23]), \
          "=r"((r)[24]),"=r"((r)[25]),"=r"((r)[26]),"=r"((r)[27]),"=r"((r)[28]),"=r"((r)[29]),"=r"((r)[30]),"=r"((r)[31]) \
        : "r"(ta))

static constexpr uint64_t SMEM_DESC_BASE_SW128 =
    (uint64_t(2) << 61) | (uint64_t(1) << 46) | (uint64_t(64) << 32) | (uint64_t(1) << 16);
__device__ __forceinline__ uint64_t make_desc(uint32_t addr) {
    return SMEM_DESC_BASE_SW128 | ((uint64_t)(addr >> 4) & 0x3FFF);
}
__device__ __forceinline__ void mma_tf32_ss(uint32_t d, uint64_t a, uint64_t b,
                                            uint32_t idesc, uint32_t en) {
    asm volatile("{\n\t.reg .pred p;\n\tsetp.ne.u32 p, %5, 0;\n\t"
        "tcgen05.mma.cta_group::1.kind::tf32 [%0], %1, %2, %3, {%4, %4, %4, %4}, p;\n\t}"
        :: "r"(d), "l"(a), "l"(b), "r"(idesc), "r"(0u), "r"(en) : "memory");
}
// dtype=f32 | atype=tf32 | btype=tf32 | N=256 | M=128
static constexpr uint32_t IDESC = (1u << 4) | (2u << 7) | (2u << 10) |
                                  ((TN / 8) << 17) | ((128 / 16) << 24);
#endif  // HAS_TCGEN05

// ---------------- index construction ----------------
__global__ void k_zero() { if (threadIdx.x < N_CLS) g_cnt[threadIdx.x] = 0; }

__global__ void k_hist(const int* __restrict__ lab) {
    int i = blockIdx.x * blockDim.x + threadIdx.x;
    if (i < N_REL) atomicAdd(&g_cnt[lab[i]], 1);
}
__global__ void k_scan() {
    if (threadIdx.x == 0) {
        int run = 0, prun = 0;
        g_off[0] = 0;
        for (int c = 0; c < N_CLS; c++) {
            g_poff[c] = prun;
            int cnt = g_cnt[c];
            run += cnt; g_off[c + 1] = run;
            prun += (cnt > 0) ? (cnt - 1) : 0;
        }
    }
}
__global__ void k_rank(const int* __restrict__ lab) {
    const int c = blockIdx.x, tid = threadIdx.x;
    __shared__ int wsum[8];
    const int base_off = g_off[c];
    int sbase = 0;
    for (int start = 0; start < N_REL; start += 256) {
        int i = start + tid;
        int flag = (lab[i] == c) ? 1 : 0;
        unsigned mask = __ballot_sync(0xffffffffu, flag);
        if ((tid & 31) == 0) wsum[tid >> 5] = __popc(mask);
        __syncthreads();
        int wbase = 0, total = 0, wi = tid >> 5;
        #pragma unroll
        for (int j = 0; j < 8; j++) { int v = wsum[j]; total += v; if (j < wi) wbase += v; }
        if (flag) {
            int excl = __popc(mask & ((1u << (tid & 31)) - 1u));
            g_sorted[base_off + sbase + wbase + excl] = i;
        }
        sbase += total;
        __syncthreads();
    }
}
__global__ void k_pairs(const int* __restrict__ lab) {
    int p = blockIdx.x * blockDim.x + threadIdx.x;
    if (p >= N_REL) return;
    int io = g_sorted[p];
    int c = lab[io];
    if (p + 1 < g_off[c + 1]) {
        int m = p - g_off[c] + g_poff[c];
        g_lo[m] = io; g_hi[m] = g_sorted[p + 1];
    }
}

// ---------------- transpose weights to K-major ----------------
__global__ void k_wt(const float* __restrict__ Wa, const float* __restrict__ Ws,
                     const float* __restrict__ Wc) {
    __shared__ float tile[32][33];
    int kb = blockIdx.x * 32;
    int ng = blockIdx.y;
    int head = ng >> 4;
    const float* W = (head == 0) ? Wa : ((head == 1) ? Ws : Wc);
    int nb = (ng & 15) * 32;
    int tx = threadIdx.x, ty = threadIdx.y;  // (32, 8)
    #pragma unroll
    for (int r = 0; r < 4; r++) {
        int k = kb + ty + r * 8;
        tile[ty + r * 8][tx] = W[(size_t)k * D_OUT + nb + tx];
    }
    __syncthreads();
    #pragma unroll
    for (int r = 0; r < 4; r++) {
        int n = ng * 32 + ty + r * 8;
        g_wt[(size_t)n * D_FEAT + kb + tx] = tile[tx][ty + r * 8];
    }
}

// ---------------- output diff epilogue: out = Y[hi] - Y[lo] + bias ----------------
__global__ void k_out(const float* __restrict__ ba, const float* __restrict__ bs,
                      const float* __restrict__ bc, float* __restrict__ out, int M) {
    const int m = blockIdx.x;
    const int hi = g_hi[m], lo = g_lo[m];
    const float4* __restrict__ yh = (const float4*)(g_y + (size_t)hi * NTOT);
    const float4* __restrict__ yl = (const float4*)(g_y + (size_t)lo * NTOT);
    for (int q = threadIdx.x; q < NTOT / 4; q += blockDim.x) {
        int col = q * 4;
        int h = col >> 9;              // head
        int c = col & 511;             // col within head
        const float* bias = (h == 0) ? ba : ((h == 1) ? bs : bc);
        float4 a = yh[q], b = yl[q];
        float4 bb = *(const float4*)(bias + c);
        float4 o;
        o.x = a.x - b.x + bb.x; o.y = a.y - b.y + bb.y;
        o.z = a.z - b.z + bb.z; o.w = a.w - b.w + bb.w;
        *(float4*)(out + ((size_t)h * M + m) * D_OUT + c) = o;
    }
}

// ---------------- GEMM: Y = X @ Wt^T (no bias) ----------------
// grid: x = 6 N-tiles (256 cols), y = 256 M-tiles (256 rows); 256 threads.
__global__ __launch_bounds__(256, 1)
void k_gemm(const __grid_constant__ CUtensorMap tmA,
            const __grid_constant__ CUtensorMap tmB,
            const float* __restrict__ X,
            const float* __restrict__ Wa, const float* __restrict__ Ws,
            const float* __restrict__ Wc, float* __restrict__ y) {
    extern __shared__ char smem[];
#if HAS_TCGEN05
    // ======================= tcgen05 tf32 + TMA path =======================
    const uint32_t sb = smem_to_u32(smem);
    // layout: [0..4) tmem ptr | [8..32) full[3] | [32..56) empty[3] | data @1024
    const uint32_t full0  = sb + 8;
    const uint32_t empty0 = sb + 32;
    const uint32_t data = (sb + 56 + 1023) & ~1023u;

    const int tid = threadIdx.x;
    const int wid = tid >> 5;
    const int lid = tid & 31;
    const int m0 = blockIdx.y * TM;
    const int n0 = blockIdx.x * TN;

    if (wid == 0) TCGEN05_ALLOC(sb, 512);
    if (tid == 0) {
        #pragma unroll
        for (int s = 0; s < STAGES; s++) {
            MBARRIER_INIT(full0 + s * 8, 1);     // expect_tx thread arrives
            MBARRIER_INIT(empty0 + s * 8, 1);    // tcgen05 commit arrives
        }
    }
    __syncthreads();
    uint32_t tmem;
    asm volatile("ld.shared.b32 %0, [%1];" : "=r"(tmem) : "r"(sb));

    const bool leader = (wid == 0) && elect_one_pred();

    if (leader) {
        // prologue: fill all stages
        #pragma unroll
        for (int i = 0; i < STAGES; i++) {
            uint32_t A_base = data + (uint32_t)i * STAGE_BYTES;
            MBARRIER_EXPECT_TX(full0 + i * 8, 2 * 32768u);
            TMA_LOAD_2D(A_base,          &tmA, i * KCHUNK, m0, full0 + i * 8);
            TMA_LOAD_2D(A_base + 32768u, &tmB, i * KCHUNK, n0, full0 + i * 8);
        }
        int s = 0, ph = 0;   // ph = (i / STAGES) & 1
        for (int i = 0; i < NK; i++) {
            const uint32_t A_base = data + (uint32_t)s * STAGE_BYTES;
            const uint32_t B_base = A_base + 32768u;
            MBARRIER_WAIT_PARITY(full0 + s * 8, ph);    // tiles arrived
            uint64_t ad0 = make_desc(A_base);
            uint64_t ad1 = make_desc(A_base + 16384u);   // rows 128..255
            uint64_t bd  = make_desc(B_base);
            #pragma unroll
            for (int ks = 0; ks < 4; ks++) {
                uint32_t en = (i > 0 || ks > 0) ? 1u : 0u;
                mma_tf32_ss(tmem,       ad0 + ks * 2, bd + ks * 2, IDESC, en);
                mma_tf32_ss(tmem + 256, ad1 + ks * 2, bd + ks * 2, IDESC, en);
            }
            TCGEN05_COMMIT(empty0 + s * 8);
            const int j = i + STAGES;
            if (j < NK) {
                // reuse stage s: wait for chunk i's MMAs to finish reading it
                MBARRIER_WAIT_PARITY(empty0 + s * 8, ph);
                MBARRIER_EXPECT_TX(full0 + s * 8, 2 * 32768u);
                TMA_LOAD_2D(A_base, &tmA, j * KCHUNK, m0, full0 + s * 8);
                TMA_LOAD_2D(B_base, &tmB, j * KCHUNK, n0, full0 + s * 8);
            }
            if (++s == STAGES) { s = 0; ph ^= 1; }
        }
        // leader is phase-paced: this waits for the FINAL commit (chunk NK-1)
        MBARRIER_WAIT_PARITY(empty0 + ((NK - 1) % STAGES) * 8, ((NK - 1) / STAGES) & 1);
    }
    __syncthreads();          // release all warps only after leader saw final commit
    TCGEN05_FENCE_AFTER();

    // epilogue: warps 0-3 -> rows m0..m0+127 (TMEM cols 0..255),
    //           warps 4-7 -> rows m0+128..m0+255 (TMEM cols 256..511)
    const uint32_t dbase = tmem + ((wid >= 4) ? 256u : 0u);
    const int m = m0 + ((wid >= 4) ? 128 : 0) + (wid & 3) * 32 + lid;
    float* dst_row = y + (size_t)m * NTOT + n0;

    #pragma unroll
    for (int cc = 0; cc < 256; cc += 32) {
        uint32_t r[32];
        TCGEN05_LD_X32(r, dbase + cc);
        TCGEN05_WAIT_LD();
        #pragma unroll
        for (int q = 0; q < 8; q++) {
            float4 o;
            o.x = __uint_as_float(r[q * 4 + 0]);
            o.y = __uint_as_float(r[q * 4 + 1]);
            o.z = __uint_as_float(r[q * 4 + 2]);
            o.w = __uint_as_float(r[q * 4 + 3]);
            *(float4*)(dst_row + cc + q * 4) = o;
        }
    }
    TCGEN05_FENCE_BEFORE();
    __syncthreads();
    if (wid == 0) {
        TCGEN05_RELINQ();
        TCGEN05_DEALLOC(tmem, 512);
    }
#else
    // ======================= SIMT fallback (compute_103 pass) =======================
    float (*As)[128] = (float(*)[128])smem;                       // [16][128]
    float (*Bs)[128] = (float(*)[128])(smem + 16 * 128 * 4);      // [16][128]
    const int tid = threadIdx.x;
    const int tx = tid & 15;
    const int ty = tid >> 4;

    for (int mh = 0; mh < 2; mh++) {
        const int m0 = blockIdx.y * TM + mh * 128;
        for (int h = 0; h < 2; h++) {
            const int n0 = blockIdx.x * TN + h * 128;
            const int head = n0 / D_OUT;
            const int ncl = n0 % D_OUT;
            const float* __restrict__ W = (head == 0) ? Wa : ((head == 1) ? Ws : Wc);

            float acc[8][8];
            #pragma unroll
            for (int i = 0; i < 8; i++)
                #pragma unroll
                for (int j = 0; j < 8; j++) acc[i][j] = 0.0f;

            for (int k0 = 0; k0 < D_FEAT; k0 += 16) {
                #pragma unroll
                for (int jj = 0; jj < 2; jj++) {
                    int idx = tid * 2 + jj;
                    int row = idx >> 2, kq = idx & 3;
                    float4 v = *(const float4*)(X + (size_t)(m0 + row) * D_FEAT + k0 + kq * 4);
                    As[kq * 4 + 0][row] = v.x; As[kq * 4 + 1][row] = v.y;
                    As[kq * 4 + 2][row] = v.z; As[kq * 4 + 3][row] = v.w;
                }
                #pragma unroll
                for (int jj = 0; jj < 2; jj++) {
                    int l = tid * 2 + jj;
                    int k = l >> 5, nq = l & 31;
                    *(float4*)&Bs[k][nq * 4] =
                        *(const float4*)(W + (size_t)(k0 + k) * D_OUT + ncl + nq * 4);
                }
                __syncthreads();
                #pragma unroll
                for (int k = 0; k < 16; k++) {
                    float4 a0 = *(const float4*)&As[k][ty * 8];
                    float4 a1 = *(const float4*)&As[k][ty * 8 + 4];
                    float4 b0 = *(const float4*)&Bs[k][tx * 8];
                    float4 b1 = *(const float4*)&Bs[k][tx * 8 + 4];
                    float av[8] = {a0.x, a0.y, a0.z, a0.w, a1.x, a1.y, a1.z, a1.w};
                    float bv[8] = {b0.x, b0.y, b0.z, b0.w, b1.x, b1.y, b1.z, b1.w};
                    #pragma unroll
                    for (int i = 0; i < 8; i++)
                        #pragma unroll
                        for (int j = 0; j < 8; j++)
                            acc[i][j] = fmaf(av[i], bv[j], acc[i][j]);
                }
                __syncthreads();
            }

            #pragma unroll
            for (int i = 0; i < 8; i++) {
                int gm = m0 + ty * 8 + i;
                float* dst = y + (size_t)gm * NTOT + n0 + tx * 8;
                float4 o0, o1;
                o0.x = acc[i][0]; o0.y = acc[i][1]; o0.z = acc[i][2]; o0.w = acc[i][3];
                o1.x = acc[i][4]; o1.y = acc[i][5]; o1.z = acc[i][6]; o1.w = acc[i][7];
                *(float4*)(dst)     = o0;
                *(float4*)(dst + 4) = o1;
            }
            __syncthreads();
        }
    }
#endif
}

// ---------------- launch ----------------
typedef CUresult (*encode_fn_t)(CUtensorMap*, CUtensorMapDataType, cuuint32_t, void*,
                                const cuuint64_t*, const cuuint64_t*, const cuuint32_t*,
                                const cuuint32_t*, CUtensorMapInterleave, CUtensorMapSwizzle,
                                CUtensorMapL2promotion, CUtensorMapFloatOOBfill);

static void make_tmap(encode_fn_t enc, CUtensorMap* tm, void* base,
                      unsigned long long rows) {
    cuuint64_t dims[2]    = { (cuuint64_t)D_FEAT, (cuuint64_t)rows };
    cuuint64_t strides[1] = { (cuuint64_t)D_FEAT * sizeof(float) };
    cuuint32_t box[2]     = { KCHUNK, 256u };
    cuuint32_t estr[2]    = { 1u, 1u };
    enc(tm, CU_TENSOR_MAP_DATA_TYPE_FLOAT32, 2, base, dims, strides, box, estr,
        CU_TENSOR_MAP_INTERLEAVE_NONE, CU_TENSOR_MAP_SWIZZLE_128B,
        CU_TENSOR_MAP_L2_PROMOTION_L2_128B, CU_TENSOR_MAP_FLOAT_OOB_FILL_NONE);
}

extern "C" void kernel_launch(void* const* d_in, const int* in_sizes, int n_in,
                              void* d_out, int out_size) {
    const float* X   = (const float*)d_in[0];
    const float* Wa  = (const float*)d_in[1];
    const float* ba  = (const float*)d_in[2];
    const float* Ws  = (const float*)d_in[3];
    const float* bs  = (const float*)d_in[4];
    const float* Wc  = (const float*)d_in[5];
    const float* bc  = (const float*)d_in[6];
    const int*   lab = (const int*)d_in[7];
    float* out = (float*)d_out;

    const int M = out_size / (3 * D_OUT);
    const int SMEM_TOTAL = STAGE_BYTES * STAGES + 1024 + 128;   // ~197.8 KB

    cudaFuncSetAttribute(k_gemm, cudaFuncAttributeMaxDynamicSharedMemorySize, SMEM_TOTAL);

    // resolve cuTensorMapEncodeTiled without -lcuda
    encode_fn_t enc = nullptr;
    {
        cudaDriverEntryPointQueryResult qr;
        void* fp = nullptr;
#if CUDART_VERSION >= 12050
        cudaGetDriverEntryPointByVersion("cuTensorMapEncodeTiled", &fp, 12000,
                                         cudaEnableDefault, &qr);
#else
        cudaGetDriverEntryPoint("cuTensorMapEncodeTiled", &fp, cudaEnableDefault, &qr);
#endif
        enc = (encode_fn_t)fp;
    }
    void* wt_ptr = nullptr;
    cudaGetSymbolAddress(&wt_ptr, g_wt);
    void* y_ptr = nullptr;
    cudaGetSymbolAddress(&y_ptr, g_y);

    CUtensorMap tmA, tmB;
    make_tmap(enc, &tmA, (void*)X, N_REL);
    make_tmap(enc, &tmB, wt_ptr, NTOT);

    k_wt<<<dim3(D_FEAT / 32, NTOT / 32), dim3(32, 8)>>>(Wa, Ws, Wc);
    k_zero<<<1, 64>>>();
    k_hist<<<N_REL / 256, 256>>>(lab);
    k_scan<<<1, 32>>>();
    k_rank<<<N_CLS, 256>>>(lab);
    k_pairs<<<N_REL / 256, 256>>>(lab);

    dim3 grid(NTOT / TN, N_REL / TM);   // (6, 256)
    k_gemm<<<grid, 256, SMEM_TOTAL>>>(tmA, tmB, X, Wa, Ws, Wc, (float*)y_ptr);

    k_out<<<M, 128>>>(ba, bs, bc, out, M);
}